// round 8
// baseline (speedup 1.0000x reference)
#include <cuda_runtime.h>
#include <cstdint>

#define NN 100000
#define NE 800000
#define H  128
#define ED 32
#define FAN 288   // 2*H + ED
#define NLAYER 3

// ---------------- scratch (static device globals; no runtime alloc) ----------
__device__ float g_deg[NN];                 // in-degree (float, exact counts)
__device__ float g_agge[NN * ED];           // sum of edge_attr per dst (layer-invariant)
__device__ float g_agg[NN * H];             // sum of x[src] per dst (per layer)
__device__ float g_x1[NN * H];              // layer ping
__device__ float g_x2[NN * H];              // layer pong

// ---------------- helpers ----------------------------------------------------
__device__ __forceinline__ void red_add_v4(float* gp, float4 v) {
    asm volatile("red.global.add.v4.f32 [%0], {%1,%2,%3,%4};"
                 :: "l"(__cvta_generic_to_global(gp)),
                    "f"(v.x), "f"(v.y), "f"(v.z), "f"(v.w)
                 : "memory");
}

// ---------------- zero kernels -----------------------------------------------
__global__ void k_zero_pre() {
    int i = blockIdx.x * blockDim.x + threadIdx.x;
    const int n4e = NN * ED / 4;
    if (i < n4e) ((float4*)g_agge)[i] = make_float4(0.f, 0.f, 0.f, 0.f);
    if (i < NN / 4) ((float4*)g_deg)[i] = make_float4(0.f, 0.f, 0.f, 0.f);
}

__global__ void k_zero_agg() {
    int i = blockIdx.x * blockDim.x + threadIdx.x;
    const int n4 = NN * H / 4;
    if (i < n4) ((float4*)g_agg)[i] = make_float4(0.f, 0.f, 0.f, 0.f);
}

// ---------------- edge preprocessing: deg + agg_e (once per launch) ----------
// 8 threads per edge; each handles one float4 of edge_attr.
// edge_index arrives as int32 [2, NE]: row 0 = src, row 1 = dst.
__global__ void k_edge_pre(const int* __restrict__ ei,
                           const float* __restrict__ ea) {
    int t = blockIdx.x * blockDim.x + threadIdx.x;
    int e = t >> 3, j = t & 7;
    if (e >= NE) return;
    int dst = __ldg(&ei[NE + e]);
    float4 v = ((const float4*)(ea + (size_t)e * ED))[j];
    red_add_v4(&g_agge[(size_t)dst * ED + j * 4], v);
    if (j == 0) atomicAdd(&g_deg[dst], 1.0f);
}

// ---------------- scatter: agg[dst] += x[src] (per layer) --------------------
// warp per edge; lane handles one float4 of the 128-float row.
__global__ void k_scatter(const int* __restrict__ ei,
                          const float* __restrict__ xs) {
    int t = blockIdx.x * blockDim.x + threadIdx.x;
    int e = t >> 5, lane = t & 31;
    if (e >= NE) return;
    int src = __ldg(&ei[e]);
    int dst = __ldg(&ei[NE + e]);
    float4 v = *(const float4*)(xs + (size_t)src * H + lane * 4);
    red_add_v4(&g_agg[(size_t)dst * H + lane * 4], v);
}

// ---------------- fused GEMM + bias + leaky ----------------------------------
// out[i] = leaky( agg[i]@Wj^T + deg[i]*(x[i]@Wi^T) + agg_e[i]@We^T + deg[i]*b )
// Tile: 128 nodes x 128 outs per block, 256 threads, 8x8 per thread, BK=8.
// Whole W (128x288) kept transposed in smem (stride 132 for alignment/banks).
#define WS_STRIDE 132
#define SMEM_GEMM_BYTES ((FAN * WS_STRIDE + 8 * WS_STRIDE) * 4)

__global__ __launch_bounds__(256) void k_gemm(const float* __restrict__ xs,
                                              const float* __restrict__ W,
                                              const float* __restrict__ b,
                                              float* __restrict__ out,
                                              int last) {
    extern __shared__ float sm[];
    float* Ws = sm;                      // [FAN][WS_STRIDE] : Ws[k*132+n] = W[n][k]
    float* As = sm + FAN * WS_STRIDE;    // [8][WS_STRIDE]   : As[k*132+m]

    const int tid = threadIdx.x;

    // Preload W transposed into smem (coalesced global reads).
    for (int e = tid; e < H * FAN; e += 256) {
        int n = e / FAN, k = e - n * FAN;
        Ws[k * WS_STRIDE + n] = W[e];
    }

    const int row0 = blockIdx.x * 128;
    const int tn = (tid & 15) * 8;   // output-col base
    const int tm = (tid >> 4) * 8;   // node-row base (within tile)

    float acc[8][8];
#pragma unroll
    for (int i = 0; i < 8; i++)
#pragma unroll
        for (int j = 0; j < 8; j++) acc[i][j] = 0.f;

    // A-staging assignment: thread loads 4 consecutive k of one row.
    const int eA = tid * 4;          // 0..1020
    const int mA = eA >> 3;          // 0..127
    const int k4 = eA & 7;           // 0 or 4
    const int rowA = row0 + mA;
    const bool okA = rowA < NN;
    const float dA = okA ? g_deg[rowA] : 0.f;

    for (int c = 0; c < FAN / 8; c++) {
        __syncthreads();
        float4 v = make_float4(0.f, 0.f, 0.f, 0.f);
        if (okA) {
            int kg = c * 8 + k4;
            if (kg < 128) {
                v = *(const float4*)(g_agg + (size_t)rowA * H + kg);
            } else if (kg < 256) {
                v = *(const float4*)(xs + (size_t)rowA * H + (kg - 128));
                v.x *= dA; v.y *= dA; v.z *= dA; v.w *= dA;
            } else {
                v = *(const float4*)(g_agge + (size_t)rowA * ED + (kg - 256));
            }
        }
        As[(k4 + 0) * WS_STRIDE + mA] = v.x;
        As[(k4 + 1) * WS_STRIDE + mA] = v.y;
        As[(k4 + 2) * WS_STRIDE + mA] = v.z;
        As[(k4 + 3) * WS_STRIDE + mA] = v.w;
        __syncthreads();

#pragma unroll
        for (int kk = 0; kk < 8; kk++) {
            float a[8], bb[8];
            *(float4*)&a[0]  = *(const float4*)&As[kk * WS_STRIDE + tm];
            *(float4*)&a[4]  = *(const float4*)&As[kk * WS_STRIDE + tm + 4];
            *(float4*)&bb[0] = *(const float4*)&Ws[(c * 8 + kk) * WS_STRIDE + tn];
            *(float4*)&bb[4] = *(const float4*)&Ws[(c * 8 + kk) * WS_STRIDE + tn + 4];
#pragma unroll
            for (int i = 0; i < 8; i++)
#pragma unroll
                for (int j = 0; j < 8; j++)
                    acc[i][j] = fmaf(a[i], bb[j], acc[i][j]);
        }
    }

    // Epilogue: bias (deg-scaled) + leaky (twice on last layer: in-loop + final)
    float bv[8];
    *(float4*)&bv[0] = *(const float4*)(b + tn);
    *(float4*)&bv[4] = *(const float4*)(b + tn + 4);
#pragma unroll
    for (int i = 0; i < 8; i++) {
        int r = row0 + tm + i;
        if (r >= NN) break;
        float d = g_deg[r];
        float o[8];
#pragma unroll
        for (int j = 0; j < 8; j++) {
            float vv = acc[i][j] + d * bv[j];
            vv = vv > 0.f ? vv : 0.01f * vv;
            if (last) vv = vv > 0.f ? vv : 0.01f * vv;
            o[j] = vv;
        }
        *(float4*)(out + (size_t)r * H + tn)     = *(const float4*)&o[0];
        *(float4*)(out + (size_t)r * H + tn + 4) = *(const float4*)&o[4];
    }
}

// ---------------- launch -----------------------------------------------------
extern "C" void kernel_launch(void* const* d_in, const int* in_sizes, int n_in,
                              void* d_out, int out_size) {
    const float* x   = (const float*)d_in[0];
    const int*   ei  = (const int*)d_in[1];   // int32 [2, NE]
    const float* ea  = (const float*)d_in[2];
    const float* Wm  = (const float*)d_in[3];
    const float* bm  = (const float*)d_in[4];
    float*       out = (float*)d_out;

    cudaFuncSetAttribute(k_gemm, cudaFuncAttributeMaxDynamicSharedMemorySize,
                         SMEM_GEMM_BYTES);

    float* d_x1; cudaGetSymbolAddress((void**)&d_x1, g_x1);
    float* d_x2; cudaGetSymbolAddress((void**)&d_x2, g_x2);

    // One-time (per launch): degree + edge-attr aggregation
    k_zero_pre<<<(NN * ED / 4 + 255) / 256, 256>>>();
    k_edge_pre<<<(NE * 8) / 256, 256>>>(ei, ea);

    // Layer 0: x -> g_x1
    k_zero_agg<<<(NN * H / 4 + 255) / 256, 256>>>();
    k_scatter<<<(NE * 32) / 256, 256>>>(ei, x);
    k_gemm<<<(NN + 127) / 128, 256, SMEM_GEMM_BYTES>>>(x, Wm, bm, d_x1, 0);

    // Layer 1: g_x1 -> g_x2
    k_zero_agg<<<(NN * H / 4 + 255) / 256, 256>>>();
    k_scatter<<<(NE * 32) / 256, 256>>>(ei, d_x1);
    k_gemm<<<(NN + 127) / 128, 256, SMEM_GEMM_BYTES>>>(d_x1, Wm + (size_t)1 * H * FAN,
                                                       bm + 1 * H, d_x2, 0);

    // Layer 2: g_x2 -> out (extra final leaky fused)
    k_zero_agg<<<(NN * H / 4 + 255) / 256, 256>>>();
    k_scatter<<<(NE * 32) / 256, 256>>>(ei, d_x2);
    k_gemm<<<(NN + 127) / 128, 256, SMEM_GEMM_BYTES>>>(d_x2, Wm + (size_t)2 * H * FAN,
                                                       bm + 2 * H, out, 1);
}

// round 13
// speedup vs baseline: 1.1057x; 1.1057x over previous
#include <cuda_runtime.h>
#include <cstdint>

#define NN 100000
#define NE 800000
#define H  128
#define ED 32
#define FAN 288   // 2*H + ED
#define NLAYER 3

// ---------------- scratch (static device globals; no runtime alloc) ----------
__device__ float g_deg[NN];                 // in-degree (float, exact counts)
__device__ float g_agge[NN * ED];           // sum of edge_attr per dst (layer-invariant)
__device__ float g_agg[NN * H];             // sum of x[src] per dst (per layer)
__device__ float g_x1[NN * H];              // layer ping
__device__ float g_x2[NN * H];              // layer pong

// ---------------- helpers ----------------------------------------------------
__device__ __forceinline__ void red_add_v4(float* gp, float4 v) {
    asm volatile("red.global.add.v4.f32 [%0], {%1,%2,%3,%4};"
                 :: "l"(__cvta_generic_to_global(gp)),
                    "f"(v.x), "f"(v.y), "f"(v.z), "f"(v.w)
                 : "memory");
}

// ---------------- zero kernels -----------------------------------------------
__global__ void k_zero_pre() {
    int i = blockIdx.x * blockDim.x + threadIdx.x;
    const int n4e = NN * ED / 4;
    if (i < n4e) ((float4*)g_agge)[i] = make_float4(0.f, 0.f, 0.f, 0.f);
    if (i < NN / 4) ((float4*)g_deg)[i] = make_float4(0.f, 0.f, 0.f, 0.f);
}

__global__ void k_zero_agg() {
    int i = blockIdx.x * blockDim.x + threadIdx.x;
    const int n4 = NN * H / 4;
    if (i < n4) ((float4*)g_agg)[i] = make_float4(0.f, 0.f, 0.f, 0.f);
}

// ---------------- edge preprocessing: deg + agg_e (once per launch) ----------
// 8 threads per edge; each handles one float4 of edge_attr.
// edge_index arrives as int32 [2, NE]: row 0 = src, row 1 = dst.
__global__ void k_edge_pre(const int* __restrict__ ei,
                           const float* __restrict__ ea) {
    int t = blockIdx.x * blockDim.x + threadIdx.x;
    int e = t >> 3, j = t & 7;
    if (e >= NE) return;
    int dst = __ldg(&ei[NE + e]);
    float4 v = ((const float4*)(ea + (size_t)e * ED))[j];
    red_add_v4(&g_agge[(size_t)dst * ED + j * 4], v);
    if (j == 0) atomicAdd(&g_deg[dst], 1.0f);
}

// ---------------- scatter: agg[dst] += x[src] (per layer) --------------------
// warp per TWO edges; lane handles one float4 of each 128-float row.
// Both gathers issued before either RED -> MLP=2 to cover L2 latency.
__global__ void k_scatter(const int* __restrict__ ei,
                          const float* __restrict__ xs) {
    int t = blockIdx.x * blockDim.x + threadIdx.x;
    int e0 = (t >> 5) * 2, lane = t & 31;
    if (e0 >= NE) return;
    int src0 = __ldg(&ei[e0]);
    int src1 = __ldg(&ei[e0 + 1]);
    int dst0 = __ldg(&ei[NE + e0]);
    int dst1 = __ldg(&ei[NE + e0 + 1]);
    float4 v0 = *(const float4*)(xs + (size_t)src0 * H + lane * 4);
    float4 v1 = *(const float4*)(xs + (size_t)src1 * H + lane * 4);
    red_add_v4(&g_agg[(size_t)dst0 * H + lane * 4], v0);
    red_add_v4(&g_agg[(size_t)dst1 * H + lane * 4], v1);
}

// ---------------- fused GEMM + bias + leaky ----------------------------------
// out[i] = leaky( agg[i]@Wj^T + deg[i]*(x[i]@Wi^T) + agg_e[i]@We^T + deg[i]*b )
// Tile: 128 nodes x 128 outs per block, 256 threads, 8x8 per thread, BK=8.
// Whole W (128x288) transposed in smem; A staged through DOUBLE-BUFFERED
// 8-row panels: next chunk's LDG issued before the FFMA block (latency hidden
// under ~2048 cyc of compute), stored to the idle buffer, ONE sync per iter.
#define WS_STRIDE 132
#define ABUF (8 * WS_STRIDE)
#define SMEM_GEMM_BYTES ((FAN * WS_STRIDE + 2 * ABUF) * 4)

__global__ __launch_bounds__(256) void k_gemm(const float* __restrict__ xs,
                                              const float* __restrict__ W,
                                              const float* __restrict__ b,
                                              float* __restrict__ out,
                                              int last) {
    extern __shared__ float sm[];
    float* Ws = sm;                      // [FAN][WS_STRIDE] : Ws[k*132+n] = W[n][k]
    float* As = sm + FAN * WS_STRIDE;    // 2 x [8][WS_STRIDE]

    const int tid = threadIdx.x;

    // Preload W transposed into smem (coalesced global reads).
    for (int e = tid; e < H * FAN; e += 256) {
        int n = e / FAN, k = e - n * FAN;
        Ws[k * WS_STRIDE + n] = __ldg(&W[e]);
    }

    const int row0 = blockIdx.x * 128;
    const int tn = (tid & 15) * 8;   // output-col base
    const int tm = (tid >> 4) * 8;   // node-row base (within tile)

    // A-staging assignment: thread loads 4 consecutive k of one row.
    const int eA = tid * 4;          // 0..1020
    const int mA = eA >> 3;          // 0..127
    const int k4 = eA & 7;           // 0 or 4
    const int rowA = row0 + mA;
    const bool okA = rowA < NN;
    const float dA = okA ? g_deg[rowA] : 0.f;

    auto load_chunk = [&](int c) -> float4 {
        float4 v = make_float4(0.f, 0.f, 0.f, 0.f);
        if (okA) {
            int kg = c * 8 + k4;
            if (kg < 128) {
                v = *(const float4*)(g_agg + (size_t)rowA * H + kg);
            } else if (kg < 256) {
                v = *(const float4*)(xs + (size_t)rowA * H + (kg - 128));
                v.x *= dA; v.y *= dA; v.z *= dA; v.w *= dA;
            } else {
                v = *(const float4*)(g_agge + (size_t)rowA * ED + (kg - 256));
            }
        }
        return v;
    };

    float acc[8][8];
#pragma unroll
    for (int i = 0; i < 8; i++)
#pragma unroll
        for (int j = 0; j < 8; j++) acc[i][j] = 0.f;

    // Prime buffer 0 with chunk 0.
    {
        float4 v = load_chunk(0);
        As[(k4 + 0) * WS_STRIDE + mA] = v.x;
        As[(k4 + 1) * WS_STRIDE + mA] = v.y;
        As[(k4 + 2) * WS_STRIDE + mA] = v.z;
        As[(k4 + 3) * WS_STRIDE + mA] = v.w;
    }
    __syncthreads();

    const int NC = FAN / 8;  // 36
    for (int c = 0; c < NC; c++) {
        float4 vn;
        if (c + 1 < NC) vn = load_chunk(c + 1);   // LDG in flight during compute

        const float* Ab = As + (c & 1) * ABUF;
        const float* Wc = Ws + (c * 8) * WS_STRIDE;
#pragma unroll
        for (int kk = 0; kk < 8; kk++) {
            float a[8], bb[8];
            *(float4*)&a[0]  = *(const float4*)&Ab[kk * WS_STRIDE + tm];
            *(float4*)&a[4]  = *(const float4*)&Ab[kk * WS_STRIDE + tm + 4];
            *(float4*)&bb[0] = *(const float4*)&Wc[kk * WS_STRIDE + tn];
            *(float4*)&bb[4] = *(const float4*)&Wc[kk * WS_STRIDE + tn + 4];
#pragma unroll
            for (int i = 0; i < 8; i++)
#pragma unroll
                for (int j = 0; j < 8; j++)
                    acc[i][j] = fmaf(a[i], bb[j], acc[i][j]);
        }

        if (c + 1 < NC) {
            float* Bn = As + ((c + 1) & 1) * ABUF;  // idle buffer this iter
            Bn[(k4 + 0) * WS_STRIDE + mA] = vn.x;
            Bn[(k4 + 1) * WS_STRIDE + mA] = vn.y;
            Bn[(k4 + 2) * WS_STRIDE + mA] = vn.z;
            Bn[(k4 + 3) * WS_STRIDE + mA] = vn.w;
        }
        __syncthreads();
    }

    // Epilogue: bias (deg-scaled) + leaky (twice on last layer: in-loop + final)
    float bv[8];
    *(float4*)&bv[0] = *(const float4*)(b + tn);
    *(float4*)&bv[4] = *(const float4*)(b + tn + 4);
#pragma unroll
    for (int i = 0; i < 8; i++) {
        int r = row0 + tm + i;
        if (r >= NN) break;
        float d = g_deg[r];
        float o[8];
#pragma unroll
        for (int j = 0; j < 8; j++) {
            float vv = acc[i][j] + d * bv[j];
            vv = vv > 0.f ? vv : 0.01f * vv;
            if (last) vv = vv > 0.f ? vv : 0.01f * vv;
            o[j] = vv;
        }
        *(float4*)(out + (size_t)r * H + tn)     = *(const float4*)&o[0];
        *(float4*)(out + (size_t)r * H + tn + 4) = *(const float4*)&o[4];
    }
}

// ---------------- launch -----------------------------------------------------
extern "C" void kernel_launch(void* const* d_in, const int* in_sizes, int n_in,
                              void* d_out, int out_size) {
    const float* x   = (const float*)d_in[0];
    const int*   ei  = (const int*)d_in[1];   // int32 [2, NE]
    const float* ea  = (const float*)d_in[2];
    const float* Wm  = (const float*)d_in[3];
    const float* bm  = (const float*)d_in[4];
    float*       out = (float*)d_out;

    cudaFuncSetAttribute(k_gemm, cudaFuncAttributeMaxDynamicSharedMemorySize,
                         SMEM_GEMM_BYTES);

    float* d_x1; cudaGetSymbolAddress((void**)&d_x1, g_x1);
    float* d_x2; cudaGetSymbolAddress((void**)&d_x2, g_x2);

    const int scat_grid = (NE / 2 * 32) / 256;   // 2 edges per warp

    // One-time (per launch): degree + edge-attr aggregation
    k_zero_pre<<<(NN * ED / 4 + 255) / 256, 256>>>();
    k_edge_pre<<<(NE * 8) / 256, 256>>>(ei, ea);

    // Layer 0: x -> g_x1
    k_zero_agg<<<(NN * H / 4 + 255) / 256, 256>>>();
    k_scatter<<<scat_grid, 256>>>(ei, x);
    k_gemm<<<(NN + 127) / 128, 256, SMEM_GEMM_BYTES>>>(x, Wm, bm, d_x1, 0);

    // Layer 1: g_x1 -> g_x2
    k_zero_agg<<<(NN * H / 4 + 255) / 256, 256>>>();
    k_scatter<<<scat_grid, 256>>>(ei, d_x1);
    k_gemm<<<(NN + 127) / 128, 256, SMEM_GEMM_BYTES>>>(d_x1, Wm + (size_t)1 * H * FAN,
                                                       bm + 1 * H, d_x2, 0);

    // Layer 2: g_x2 -> out (extra final leaky fused)
    k_zero_agg<<<(NN * H / 4 + 255) / 256, 256>>>();
    k_scatter<<<scat_grid, 256>>>(ei, d_x2);
    k_gemm<<<(NN + 127) / 128, 256, SMEM_GEMM_BYTES>>>(d_x2, Wm + (size_t)2 * H * FAN,
                                                       bm + 2 * H, out, 1);
}